// round 7
// baseline (speedup 1.0000x reference)
#include <cuda_runtime.h>
#include <stdint.h>
#include <math.h>

// TopkMoeFFN: N=131072, H=128, O=128, E=8, top2, fp32.
// gate(+x split emit) -> wprep -> scan -> place -> ffn x2.
// k_ffn: pre-split bf16 A/W staged via cp.async (double-buffered A),
// gate applied in epilogue. 128x128x128 bf16-split mma.sync tiles.

#define NTOK  131072
#define HDIM  128
#define ODIM  128
#define NEXP  8
#define NBLK  1024
#define GRID3 152
#define WPITCH 272
#define MAXT  1040

__device__ float4 g_meta[NTOK];
__device__ unsigned short g_r0[NTOK], g_r1[NTOK];
__device__ int g_hist0[NBLK * NEXP], g_hist1[NBLK * NEXP];
__device__ int g_base0[NBLK * NEXP], g_base1[NBLK * NEXP];
__device__ unsigned int g_tok0[NTOK], g_tok1[NTOK];
__device__ float g_gate0[NTOK], g_gate1[NTOK];
__device__ int g_te[2][MAXT], g_ts[2][MAXT], g_tv[2][MAXT];
__device__ int g_nt[2];
// pre-split operands (bf16x2 words)
__device__ uint32_t g_xhi[NTOK * 64], g_xlo[NTOK * 64];          // 33.5MB x2
__device__ uint32_t g_whi[NEXP * HDIM * 64], g_wlo[NEXP * HDIM * 64];

__device__ __forceinline__ uint32_t smem_u32(const void* p) {
    uint32_t a;
    asm("{ .reg .u64 t; cvta.to.shared.u64 t, %1; cvt.u32.u64 %0, t; }"
        : "=r"(a) : "l"(p));
    return a;
}

__device__ __forceinline__ uint32_t cvt_bf16x2(float hi, float lo) {
    uint32_t d;
    asm("cvt.rn.bf16x2.f32 %0, %1, %2;" : "=r"(d) : "f"(hi), "f"(lo));
    return d;
}

__device__ __forceinline__ void split2(float f0, float f1,
                                       uint32_t& hi, uint32_t& lo) {
    hi = cvt_bf16x2(f1, f0);
    float h0 = __uint_as_float(hi << 16);
    float h1 = __uint_as_float(hi & 0xffff0000u);
    lo = cvt_bf16x2(f1 - h1, f0 - h0);
}

__device__ __forceinline__ void ldsm_x2t(uint32_t& r0, uint32_t& r1, uint32_t a) {
    asm volatile("ldmatrix.sync.aligned.m8n8.x2.trans.shared.b16 {%0,%1}, [%2];"
                 : "=r"(r0), "=r"(r1) : "r"(a));
}

__device__ __forceinline__ void ldsm_x4(uint32_t& r0, uint32_t& r1,
                                        uint32_t& r2, uint32_t& r3, uint32_t a) {
    asm volatile("ldmatrix.sync.aligned.m8n8.x4.shared.b16 {%0,%1,%2,%3}, [%4];"
                 : "=r"(r0), "=r"(r1), "=r"(r2), "=r"(r3) : "r"(a));
}

__device__ __forceinline__ void mma16816(float* c,
                                         uint32_t a0, uint32_t a1, uint32_t a2,
                                         uint32_t a3, uint32_t b0, uint32_t b1) {
    asm volatile(
        "mma.sync.aligned.m16n8k16.row.col.f32.bf16.bf16.f32 "
        "{%0,%1,%2,%3}, {%4,%5,%6,%7}, {%8,%9}, {%0,%1,%2,%3};"
        : "+f"(c[0]), "+f"(c[1]), "+f"(c[2]), "+f"(c[3])
        : "r"(a0), "r"(a1), "r"(a2), "r"(a3), "r"(b0), "r"(b1));
}

__device__ __forceinline__ void cpa16(uint32_t dst, const void* src) {
    asm volatile("cp.async.cg.shared.global [%0], [%1], 16;"
                 :: "r"(dst), "l"(src) : "memory");
}

// ---------------- kernel 1: gating + x split emit ----------------
#define G_SX   0
#define G_SWG  (128 * 132 * 4)
#define G_SMEM (G_SWG + HDIM * NEXP * 4)

extern __shared__ char smraw[];

__global__ void __launch_bounds__(128)
k_gate(const float* __restrict__ x, const float* __restrict__ wg) {
    float* sx  = (float*)(smraw + G_SX);
    float* swg = (float*)(smraw + G_SWG);
    __shared__ int wh0[4][8], wh1[4][8];

    const int tid = threadIdx.x, lane = tid & 31, w = tid >> 5;
    const int blk = blockIdx.x, tok0 = blk * 128;

    for (int i = tid; i < HDIM * NEXP; i += 128) swg[i] = wg[i];
    const float4* xg = (const float4*)(x + (size_t)tok0 * HDIM);
    for (int i = tid; i < 128 * 32; i += 128) {
        float4 v = xg[i];
        int t = i >> 5, c = (i & 31) * 4;
        *(float4*)(sx + t * 132 + c) = v;
        // emit bf16 split (coalesced uint2 per 4 floats)
        uint32_t h0, l0, h1, l1;
        split2(v.x, v.y, h0, l0);
        split2(v.z, v.w, h1, l1);
        size_t widx = (size_t)(tok0 + t) * 32 + (i & 31);
        ((uint2*)g_xhi)[widx] = make_uint2(h0, h1);
        ((uint2*)g_xlo)[widx] = make_uint2(l0, l1);
    }
    __syncthreads();

    float lg[NEXP];
#pragma unroll
    for (int e = 0; e < NEXP; e++) lg[e] = 0.f;
    const float* xr = sx + tid * 132;
#pragma unroll 4
    for (int h4 = 0; h4 < 32; h4++) {
        float4 xq = *(const float4*)(xr + h4 * 4);
        const float* wr = swg + h4 * 32;
#pragma unroll
        for (int j = 0; j < 4; j++) {
            float xv = (j == 0) ? xq.x : (j == 1) ? xq.y : (j == 2) ? xq.z : xq.w;
            float4 wa = *(const float4*)(wr + j * 8);
            float4 wb = *(const float4*)(wr + j * 8 + 4);
            lg[0] = fmaf(xv, wa.x, lg[0]); lg[1] = fmaf(xv, wa.y, lg[1]);
            lg[2] = fmaf(xv, wa.z, lg[2]); lg[3] = fmaf(xv, wa.w, lg[3]);
            lg[4] = fmaf(xv, wb.x, lg[4]); lg[5] = fmaf(xv, wb.y, lg[5]);
            lg[6] = fmaf(xv, wb.z, lg[6]); lg[7] = fmaf(xv, wb.w, lg[7]);
        }
    }
    int i0 = 0; float v0 = lg[0];
#pragma unroll
    for (int e = 1; e < NEXP; e++)
        if (lg[e] > v0) { v0 = lg[e]; i0 = e; }
    int i1 = -1; float v1 = -3.4e38f;
#pragma unroll
    for (int e = 0; e < NEXP; e++)
        if (e != i0 && lg[e] > v1) { v1 = lg[e]; i1 = e; }
    float e1 = expf(v1 - v0);
    float g0 = 1.f / (1.f + e1);
    float g1 = e1 * g0;

    unsigned ltm = (1u << lane) - 1u;
    int myr0 = 0, myr1 = 0;
#pragma unroll
    for (int e = 0; e < NEXP; e++) {
        unsigned m0 = __ballot_sync(0xffffffffu, i0 == e);
        unsigned m1 = __ballot_sync(0xffffffffu, i1 == e);
        if (i0 == e) myr0 = __popc(m0 & ltm);
        if (i1 == e) myr1 = __popc(m1 & ltm);
        if (lane == e) { wh0[w][e] = __popc(m0); wh1[w][e] = __popc(m1); }
    }
    __syncthreads();
    int r0 = myr0, r1 = myr1;
    for (int ww = 0; ww < w; ww++) { r0 += wh0[ww][i0]; r1 += wh1[ww][i1]; }

    int token = tok0 + tid;
    g_meta[token] = make_float4(
        __uint_as_float((unsigned)i0 | ((unsigned)i1 << 8)), g0, g1, 0.f);
    g_r0[token] = (unsigned short)r0;
    g_r1[token] = (unsigned short)r1;
    if (tid < NEXP) {
        g_hist0[blk * NEXP + tid] =
            wh0[0][tid] + wh0[1][tid] + wh0[2][tid] + wh0[3][tid];
        g_hist1[blk * NEXP + tid] =
            wh1[0][tid] + wh1[1][tid] + wh1[2][tid] + wh1[3][tid];
    }
}

// ---------------- kernel 1b: weight split ----------------
__global__ void __launch_bounds__(256) k_wprep(const float* __restrict__ we) {
    const int e = blockIdx.x;
    const float4* src = (const float4*)(we + (size_t)e * HDIM * ODIM);
    for (int i = threadIdx.x; i < HDIM * 32; i += 256) {
        float4 v = src[i];
        uint32_t h0, l0, h1, l1;
        split2(v.x, v.y, h0, l0);
        split2(v.z, v.w, h1, l1);
        size_t widx = (size_t)e * HDIM * 32 + i;   // uint2 index
        ((uint2*)g_whi)[widx] = make_uint2(h0, h1);
        ((uint2*)g_wlo)[widx] = make_uint2(l0, l1);
    }
}

// ---------------- kernel 2: scan ----------------
__global__ void k_scan() {
    __shared__ int s[NBLK * NEXP];
    __shared__ int scnt[NEXP], soff[NEXP], ttb[NEXP + 1];
    const int tid = threadIdx.x, lane = tid & 31, w = tid >> 5;

    for (int p = 0; p < 2; p++) {
        const int* hist = p ? g_hist1 : g_hist0;
        int* base = p ? g_base1 : g_base0;
        for (int i = tid; i < NBLK * NEXP; i += 256) s[i] = hist[i];
        __syncthreads();

        int run = 0;
        for (int j = 0; j < NBLK / 32; j++) {
            int b = j * 32 + lane;
            int v = s[b * NEXP + w];
            int incl = v;
#pragma unroll
            for (int d = 1; d < 32; d <<= 1) {
                int t = __shfl_up_sync(0xffffffffu, incl, d);
                if (lane >= d) incl += t;
            }
            int tot = __shfl_sync(0xffffffffu, incl, 31);
            s[b * NEXP + w] = run + incl - v;
            run += tot;
        }
        if (lane == 0) scnt[w] = run;
        __syncthreads();
        if (tid == 0) {
            int o = 0;
            ttb[0] = 0;
            for (int e = 0; e < NEXP; e++) {
                soff[e] = o; o += scnt[e];
                ttb[e + 1] = ttb[e] + (scnt[e] + 127) / 128;
            }
            g_nt[p] = ttb[NEXP];
        }
        __syncthreads();
        for (int i = tid; i < NBLK * NEXP; i += 256)
            base[i] = s[i] + soff[i & 7];
        const int ntt = ttb[NEXP];
        for (int idx = tid; idx < ntt; idx += 256) {
            int e = 0;
            while (ttb[e + 1] <= idx) e++;
            int i = idx - ttb[e];
            g_te[p][idx] = e;
            g_ts[p][idx] = soff[e] + i * 128;
            g_tv[p][idx] = min(128, scnt[e] - i * 128);
        }
        __syncthreads();
    }
}

// ---------------- kernel 3: scatter ----------------
__global__ void __launch_bounds__(128) k_place() {
    const int blk = blockIdx.x;
    const int token = blk * 128 + threadIdx.x;
    float4 m = g_meta[token];
    unsigned u = __float_as_uint(m.x);
    int e0 = u & 0xff, e1 = (u >> 8) & 0xff;
    int s0 = g_base0[blk * NEXP + e0] + g_r0[token];
    int s1 = g_base1[blk * NEXP + e1] + g_r1[token];
    g_tok0[s0] = (unsigned)token; g_gate0[s0] = m.y;
    g_tok1[s1] = (unsigned)token; g_gate1[s1] = m.z;
}

// ---------------- kernel 4: pipelined FFN GEMM ----------------
#define F_WHI   0
#define F_WLO   34816
#define F_A0HI  69632
#define F_A0LO  104448
#define F_A1HI  139264
#define F_A1LO  174080
#define F_BIAS  208896
#define F_TOK   212992      // 2 x 128 int
#define F_SGT   214016      // 2 x 128 float
#define F_META  215040      // 2 x 128 float4
#define F_SMEM  219136
#define NTHR_F 512

__global__ void __launch_bounds__(NTHR_F, 1)
k_ffn(const float* __restrict__ be, float* __restrict__ out, int p) {
    const int tid = threadIdx.x, lane = tid & 31, w = tid >> 5;
    float* sbias = (float*)(smraw + F_BIAS);
    int* stok = (int*)(smraw + F_TOK);
    float* sgt = (float*)(smraw + F_SGT);
    float4* smeta = (float4*)(smraw + F_META);
    const uint32_t su = smem_u32(smraw);

    const unsigned* tokl = p ? g_tok1 : g_tok0;
    const float* gatel   = p ? g_gate1 : g_gate0;

    const int ntiles = g_nt[p];
    const int t0 = (int)((long long)blockIdx.x * ntiles / GRID3);
    const int t1 = (int)((long long)(blockIdx.x + 1) * ntiles / GRID3);
    if (t0 >= t1) return;

    for (int i = tid; i < NEXP * ODIM; i += NTHR_F) sbias[i] = be[i];

    const int mt = w >> 2, nq = w & 3;
    const int grp = lane >> 3;
    const int ar = (lane & 7) + ((grp & 1) ? 8 : 0);
    const int ac = (grp >> 1) * 8;
    const uint32_t a_off0 = (uint32_t)(mt * 32 + ar) * WPITCH + (uint32_t)ac * 2;
    const uint32_t b_base = su + F_WHI + (uint32_t)(lane & 15) * WPITCH
                          + (uint32_t)nq * 64u;

    const int row = tid >> 2, q = tid & 3;
    const uint32_t a_dst_off = (uint32_t)row * WPITCH + (uint32_t)q * 64u;

    // prologue: load tokens for t0, prefetch A(t0) into buf0
    unsigned nx_token; float nx_gate;
    {
        int s0 = g_ts[p][t0], v0 = g_tv[p][t0];
        nx_token = 0; nx_gate = 0.f;
        if (row < v0) { nx_token = tokl[s0 + row]; nx_gate = gatel[s0 + row]; }
        const char* shi = (const char*)g_xhi + (size_t)nx_token * 256 + q * 64;
        const char* slo = (const char*)g_xlo + (size_t)nx_token * 256 + q * 64;
#pragma unroll
        for (int i = 0; i < 4; i++) {
            cpa16(su + F_A0HI + a_dst_off + i * 16, shi + i * 16);
            cpa16(su + F_A0LO + a_dst_off + i * 16, slo + i * 16);
        }
        asm volatile("cp.async.commit_group;" ::: "memory");
    }

    int cur_e = -1;
    for (int t = t0; t < t1; t++) {
        const int cb = (t - t0) & 1;
        const int e = g_te[p][t];
        const int valid = g_tv[p][t];
        const unsigned token = nx_token;
        const float gv = nx_gate;

        if (t + 1 < t1) {
            int s0n = g_ts[p][t + 1], vn = g_tv[p][t + 1];
            nx_token = 0; nx_gate = 0.f;
            if (row < vn) { nx_token = tokl[s0n + row]; nx_gate = gatel[s0n + row]; }
        }

        __syncthreads();   // GEMM(t-1) complete: other A buf + W writable

        // W stage on expert change (cp.async from pre-split global)
        if (e != cur_e) {
            const char* whi = (const char*)g_whi + (size_t)e * 32768;
            const char* wlo = (const char*)g_wlo + (size_t)e * 32768;
            for (int i = tid; i < 4096; i += NTHR_F) {
                int half = i >> 11;          // 0=hi, 1=lo
                int j = i & 2047;
                int h = j >> 4, c = j & 15;
                const char* src = (half ? wlo : whi) + h * 256 + c * 16;
                uint32_t dst = su + (half ? F_WLO : F_WHI)
                             + (uint32_t)h * WPITCH + (uint32_t)c * 16;
                cpa16(dst, src);
            }
            cur_e = e;
        }
        asm volatile("cp.async.commit_group;" ::: "memory");   // W group

        // prefetch A(t+1) into other buffer
        if (t + 1 < t1) {
            const uint32_t abuf = cb ? F_A0HI : F_A1HI;
            const uint32_t lbuf = cb ? F_A0LO : F_A1LO;
            const char* shi = (const char*)g_xhi + (size_t)nx_token * 256 + q * 64;
            const char* slo = (const char*)g_xlo + (size_t)nx_token * 256 + q * 64;
#pragma unroll
            for (int i = 0; i < 4; i++) {
                cpa16(su + abuf + a_dst_off + i * 16, shi + i * 16);
                cpa16(su + lbuf + a_dst_off + i * 16, slo + i * 16);
            }
        }
        asm volatile("cp.async.commit_group;" ::: "memory");   // A(t+1) group

        if (q == 0) {
            stok[cb * 128 + row] = (int)token;
            sgt[cb * 128 + row] = gv;
            if (p == 0) smeta[cb * 128 + row] = g_meta[token];
        }

        asm volatile("cp.async.wait_group 1;" ::: "memory");   // A(t)+W(t) done
        __syncthreads();

        // GEMM on buffer cb
        const uint32_t a_hi = su + (cb ? F_A1HI : F_A0HI) + a_off0;
        float acc[2][4][4], accB[2][4][4];
#pragma unroll
        for (int m = 0; m < 2; m++)
#pragma unroll
            for (int nt = 0; nt < 4; nt++)
#pragma unroll
                for (int j = 0; j < 4; j++) {
                    acc[m][nt][j] = 0.f; accB[m][nt][j] = 0.f;
                }

#pragma unroll
        for (int kb = 0; kb < 8; kb++) {
            uint32_t ah[2][4], al[2][4];
            uint32_t aa0 = a_hi + (uint32_t)kb * 32;
            uint32_t aa1 = aa0 + 16u * WPITCH;
            ldsm_x4(ah[0][0], ah[0][1], ah[0][2], ah[0][3], aa0);
            ldsm_x4(al[0][0], al[0][1], al[0][2], al[0][3], aa0 + 34816u);
            ldsm_x4(ah[1][0], ah[1][1], ah[1][2], ah[1][3], aa1);
            ldsm_x4(al[1][0], al[1][1], al[1][2], al[1][3], aa1 + 34816u);
            uint32_t bb = b_base + (uint32_t)kb * 16 * WPITCH;
#pragma unroll
            for (int nt = 0; nt < 4; nt++) {
                uint32_t bh0, bh1, bl0, bl1;
                ldsm_x2t(bh0, bh1, bb + nt * 16);
                ldsm_x2t(bl0, bl1, bb + nt * 16 + (F_WLO - F_WHI));
#pragma unroll
                for (int m = 0; m < 2; m++) {
                    mma16816(acc[m][nt], ah[m][0], ah[m][1], ah[m][2], ah[m][3],
                             bh0, bh1);
                    mma16816(accB[m][nt], ah[m][0], ah[m][1], ah[m][2], ah[m][3],
                             bl0, bl1);
                    mma16816(accB[m][nt], al[m][0], al[m][1], al[m][2], al[m][3],
                             bh0, bh1);
                }
            }
        }

        // epilogue: scale by per-row gate
        const int qr = lane >> 2, qk = (lane & 3) * 2;
#pragma unroll
        for (int m = 0; m < 2; m++) {
            int ra = mt * 32 + m * 16 + qr;
            int rb = ra + 8;
            bool va = ra < valid, vb = rb < valid;
            float* opa = va ? out + (size_t)stok[cb * 128 + ra] * ODIM : 0;
            float* opb = vb ? out + (size_t)stok[cb * 128 + rb] * ODIM : 0;
            float ga = va ? sgt[cb * 128 + ra] : 0.f;
            float gb = vb ? sgt[cb * 128 + rb] : 0.f;
            if (p == 0) {
#pragma unroll
                for (int hrow = 0; hrow < 2; hrow++) {
                    int r = hrow ? rb : ra;
                    float* op = hrow ? opb : opa;
                    float g = hrow ? gb : ga;
                    if (!(hrow ? vb : va)) continue;
                    float4 mm = smeta[cb * 128 + r];
                    unsigned u = __float_as_uint(mm.x);
                    const float* b0p = sbias + (u & 0xff) * ODIM;
                    const float* b1p = sbias + ((u >> 8) & 0xff) * ODIM;
                    float gg0 = mm.y, gg1 = mm.z;
                    const int ci = hrow * 2;
#pragma unroll
                    for (int nt = 0; nt < 4; nt++) {
                        int col = nq * 32 + nt * 8 + qk;
                        float2 v;
                        v.x = g * (acc[m][nt][ci] + accB[m][nt][ci])
                            + gg0 * b0p[col] + gg1 * b1p[col];
                        v.y = g * (acc[m][nt][ci + 1] + accB[m][nt][ci + 1])
                            + gg0 * b0p[col + 1] + gg1 * b1p[col + 1];
                        *(float2*)(op + col) = v;
                    }
                }
            } else {
                float2 o[2][4];
#pragma unroll
                for (int nt = 0; nt < 4; nt++) {
                    int col = nq * 32 + nt * 8 + qk;
                    if (va) o[0][nt] = *(float2*)(opa + col);
                    if (vb) o[1][nt] = *(float2*)(opb + col);
                }
#pragma unroll
                for (int nt = 0; nt < 4; nt++) {
                    int col = nq * 32 + nt * 8 + qk;
                    if (va) {
                        float2 v = o[0][nt];
                        v.x += ga * (acc[m][nt][0] + accB[m][nt][0]);
                        v.y += ga * (acc[m][nt][1] + accB[m][nt][1]);
                        *(float2*)(opa + col) = v;
                    }
                    if (vb) {
                        float2 v = o[1][nt];
                        v.x += gb * (acc[m][nt][2] + accB[m][nt][2]);
                        v.y += gb * (acc[m][nt][3] + accB[m][nt][3]);
                        *(float2*)(opb + col) = v;
                    }
                }
            }
        }
    }
}

// ---------------- launch ----------------
extern "C" void kernel_launch(void* const* d_in, const int* in_sizes, int n_in,
                              void* d_out, int out_size) {
    const float* x  = (const float*)d_in[0];
    const float* wg = (const float*)d_in[1];
    // d_in[2] = w_noise (inactive in eval mode)
    const float* we = (const float*)d_in[3];
    const float* be = (const float*)d_in[4];
    float* out = (float*)d_out;

    cudaFuncSetAttribute(k_gate, cudaFuncAttributeMaxDynamicSharedMemorySize,
                         G_SMEM);
    cudaFuncSetAttribute(k_ffn, cudaFuncAttributeMaxDynamicSharedMemorySize,
                         F_SMEM);

    k_gate<<<NBLK, 128, G_SMEM>>>(x, wg);
    k_wprep<<<NEXP, 256>>>(we);
    k_scan<<<1, 256>>>();
    k_place<<<NBLK, 128>>>();
    k_ffn<<<GRID3, NTHR_F, F_SMEM>>>(be, out, 0);
    k_ffn<<<GRID3, NTHR_F, F_SMEM>>>(be, out, 1);
}

// round 8
// speedup vs baseline: 1.2604x; 1.2604x over previous
#include <cuda_runtime.h>
#include <stdint.h>
#include <math.h>

// TopkMoeFFN: N=131072, H=128, O=128, E=8, top2, fp32.
// zero -> gate (atomic slot alloc) -> ffn x2 phases.
// Dense expert-sorted 128x128x128 bf16-split mma.sync tiles,
// cp.async-pipelined A gather, x4.trans B ldmatrix.

#define NTOK  131072
#define HDIM  128
#define ODIM  128
#define NEXP  8
#define NBLK  1024
#define GRID3 152
#define WPITCH 272

__device__ float4 g_meta[NTOK];
__device__ int g_cnt[2][NEXP];
__device__ unsigned int g_etok[2][NEXP * NTOK];   // per-expert token lists
__device__ float g_egat[2][NEXP * NTOK];

__device__ __forceinline__ uint32_t smem_u32(const void* p) {
    uint32_t a;
    asm("{ .reg .u64 t; cvta.to.shared.u64 t, %1; cvt.u32.u64 %0, t; }"
        : "=r"(a) : "l"(p));
    return a;
}

__device__ __forceinline__ uint32_t cvt_bf16x2(float hi, float lo) {
    uint32_t d;
    asm("cvt.rn.bf16x2.f32 %0, %1, %2;" : "=r"(d) : "f"(hi), "f"(lo));
    return d;
}

__device__ __forceinline__ void split2(float f0, float f1,
                                       uint32_t& hi, uint32_t& lo) {
    hi = cvt_bf16x2(f1, f0);
    float h0 = __uint_as_float(hi << 16);
    float h1 = __uint_as_float(hi & 0xffff0000u);
    lo = cvt_bf16x2(f1 - h1, f0 - h0);
}

__device__ __forceinline__ void ldsm_x4t(uint32_t& r0, uint32_t& r1,
                                         uint32_t& r2, uint32_t& r3, uint32_t a) {
    asm volatile("ldmatrix.sync.aligned.m8n8.x4.trans.shared.b16 {%0,%1,%2,%3}, [%4];"
                 : "=r"(r0), "=r"(r1), "=r"(r2), "=r"(r3) : "r"(a));
}

__device__ __forceinline__ void ldsm_x4(uint32_t& r0, uint32_t& r1,
                                        uint32_t& r2, uint32_t& r3, uint32_t a) {
    asm volatile("ldmatrix.sync.aligned.m8n8.x4.shared.b16 {%0,%1,%2,%3}, [%4];"
                 : "=r"(r0), "=r"(r1), "=r"(r2), "=r"(r3) : "r"(a));
}

__device__ __forceinline__ void mma16816(float* c,
                                         uint32_t a0, uint32_t a1, uint32_t a2,
                                         uint32_t a3, uint32_t b0, uint32_t b1) {
    asm volatile(
        "mma.sync.aligned.m16n8k16.row.col.f32.bf16.bf16.f32 "
        "{%0,%1,%2,%3}, {%4,%5,%6,%7}, {%8,%9}, {%0,%1,%2,%3};"
        : "+f"(c[0]), "+f"(c[1]), "+f"(c[2]), "+f"(c[3])
        : "r"(a0), "r"(a1), "r"(a2), "r"(a3), "r"(b0), "r"(b1));
}

__device__ __forceinline__ void cpa16(uint32_t dst, const void* src) {
    asm volatile("cp.async.cg.shared.global [%0], [%1], 16;"
                 :: "r"(dst), "l"(src) : "memory");
}

// ---------------- kernel 0: zero counters (graph replays!) ----------------
__global__ void k_zero() {
    if (threadIdx.x < 16) ((int*)g_cnt)[threadIdx.x] = 0;
}

// ---------------- kernel 1: gating + atomic slot allocation ----------------
#define G_SX   0
#define G_SWG  (128 * 132 * 4)
#define G_SMEM (G_SWG + HDIM * NEXP * 4)

extern __shared__ char smraw[];

__global__ void __launch_bounds__(128)
k_gate(const float* __restrict__ x, const float* __restrict__ wg) {
    float* sx  = (float*)(smraw + G_SX);
    float* swg = (float*)(smraw + G_SWG);
    __shared__ int wh0[4][8], wh1[4][8];
    __shared__ int gb0[8], gb1[8];

    const int tid = threadIdx.x, lane = tid & 31, w = tid >> 5;
    const int blk = blockIdx.x, tok0 = blk * 128;

    for (int i = tid; i < HDIM * NEXP; i += 128) swg[i] = wg[i];
    const float4* xg = (const float4*)(x + (size_t)tok0 * HDIM);
    for (int i = tid; i < 128 * 32; i += 128) {
        float4 v = xg[i];
        int t = i >> 5, c = (i & 31) * 4;
        *(float4*)(sx + t * 132 + c) = v;
    }
    __syncthreads();

    float lg[NEXP];
#pragma unroll
    for (int e = 0; e < NEXP; e++) lg[e] = 0.f;
    const float* xr = sx + tid * 132;
#pragma unroll 4
    for (int h4 = 0; h4 < 32; h4++) {
        float4 xq = *(const float4*)(xr + h4 * 4);
        const float* wr = swg + h4 * 32;
#pragma unroll
        for (int j = 0; j < 4; j++) {
            float xv = (j == 0) ? xq.x : (j == 1) ? xq.y : (j == 2) ? xq.z : xq.w;
            float4 wa = *(const float4*)(wr + j * 8);
            float4 wb = *(const float4*)(wr + j * 8 + 4);
            lg[0] = fmaf(xv, wa.x, lg[0]); lg[1] = fmaf(xv, wa.y, lg[1]);
            lg[2] = fmaf(xv, wa.z, lg[2]); lg[3] = fmaf(xv, wa.w, lg[3]);
            lg[4] = fmaf(xv, wb.x, lg[4]); lg[5] = fmaf(xv, wb.y, lg[5]);
            lg[6] = fmaf(xv, wb.z, lg[6]); lg[7] = fmaf(xv, wb.w, lg[7]);
        }
    }
    int i0 = 0; float v0 = lg[0];
#pragma unroll
    for (int e = 1; e < NEXP; e++)
        if (lg[e] > v0) { v0 = lg[e]; i0 = e; }
    int i1 = -1; float v1 = -3.4e38f;
#pragma unroll
    for (int e = 0; e < NEXP; e++)
        if (e != i0 && lg[e] > v1) { v1 = lg[e]; i1 = e; }
    float e1 = expf(v1 - v0);
    float g0 = 1.f / (1.f + e1);
    float g1 = e1 * g0;

    // warp ranks + per-warp histograms
    unsigned ltm = (1u << lane) - 1u;
    int myr0 = 0, myr1 = 0;
#pragma unroll
    for (int e = 0; e < NEXP; e++) {
        unsigned m0 = __ballot_sync(0xffffffffu, i0 == e);
        unsigned m1 = __ballot_sync(0xffffffffu, i1 == e);
        if (i0 == e) myr0 = __popc(m0 & ltm);
        if (i1 == e) myr1 = __popc(m1 & ltm);
        if (lane == e) { wh0[w][e] = __popc(m0); wh1[w][e] = __popc(m1); }
    }
    __syncthreads();
    int r0 = myr0, r1 = myr1;
    for (int ww = 0; ww < w; ww++) { r0 += wh0[ww][i0]; r1 += wh1[ww][i1]; }

    // block-level atomic base allocation (8 atomics/block/phase)
    if (tid < NEXP) {
        int c0 = wh0[0][tid] + wh0[1][tid] + wh0[2][tid] + wh0[3][tid];
        int c1 = wh1[0][tid] + wh1[1][tid] + wh1[2][tid] + wh1[3][tid];
        gb0[tid] = atomicAdd(&g_cnt[0][tid], c0);
        gb1[tid] = atomicAdd(&g_cnt[1][tid], c1);
    }
    __syncthreads();

    int token = tok0 + tid;
    int s0 = gb0[i0] + r0, s1 = gb1[i1] + r1;
    g_etok[0][i0 * NTOK + s0] = (unsigned)token;
    g_egat[0][i0 * NTOK + s0] = g0;
    g_etok[1][i1 * NTOK + s1] = (unsigned)token;
    g_egat[1][i1 * NTOK + s1] = g1;
    g_meta[token] = make_float4(
        __uint_as_float((unsigned)i0 | ((unsigned)i1 << 8)), g0, g1, 0.f);
}

// ---------------- kernel 2: pipelined FFN GEMM ----------------
#define F_WHI   0
#define F_WLO   34816
#define F_AHI   69632
#define F_ALO   104448
#define F_STAGE 139264
#define F_BIAS  204800
#define F_TOK   208896
#define F_META  209408
#define F_SMEM  211456
#define NTHR_F 512

__global__ void __launch_bounds__(NTHR_F, 1)
k_ffn(const float* __restrict__ x, const float* __restrict__ we,
      const float* __restrict__ be, float* __restrict__ out, int p) {
    const int tid = threadIdx.x, lane = tid & 31, w = tid >> 5;
    float* sbias = (float*)(smraw + F_BIAS);
    int* stok = (int*)(smraw + F_TOK);
    float4* smeta = (float4*)(smraw + F_META);
    const uint32_t su = smem_u32(smraw);

    const unsigned* tokl = g_etok[p];
    const float* gatel   = g_egat[p];

    // tile map from the 8 counters (registers)
    int cnt[NEXP], tb[NEXP + 1];
    tb[0] = 0;
#pragma unroll
    for (int e = 0; e < NEXP; e++) {
        cnt[e] = g_cnt[p][e];
        tb[e + 1] = tb[e] + ((cnt[e] + 127) >> 7);
    }
    const int ntiles = tb[NEXP];
    const int t0 = (int)((long long)blockIdx.x * ntiles / GRID3);
    const int t1 = (int)((long long)(blockIdx.x + 1) * ntiles / GRID3);
    if (t0 >= t1) return;

#define TILE_ELI(t, e_, li_) do { \
        e_ = 0; \
        _Pragma("unroll") \
        for (int k_ = 0; k_ < NEXP; k_++) if (tb[k_ + 1] <= (t)) e_ = k_ + 1; \
        li_ = (t) - tb[e_]; \
    } while (0)

    for (int i = tid; i < NEXP * ODIM; i += NTHR_F) sbias[i] = be[i];

    const int mt = w >> 2, nq = w & 3;
    const int grp = lane >> 3;
    const int ar = (lane & 7) + ((grp & 1) ? 8 : 0);
    const int ac = (grp >> 1) * 8;
    const uint32_t a_base0 = su + F_AHI
                           + (uint32_t)(mt * 32 + ar) * WPITCH + (uint32_t)ac * 2;
    const uint32_t a_base1 = a_base0 + 16u * WPITCH;
    // x4.trans: lanes 16-31 fetch the adjacent n8 tile
    const uint32_t b_base = su + F_WHI + (uint32_t)(lane & 15) * WPITCH
                          + (uint32_t)nq * 64u + (uint32_t)(lane >> 4) * 16u;

    const int row = tid >> 2, q = tid & 3;
    const uint32_t stage_b = su + F_STAGE + (uint32_t)tid * 128u;
    char* stage_l = smraw + F_STAGE + tid * 128;

    // prologue: prefetch tile t0
    unsigned nx_token; float nx_gate;
    {
        int e_, li_;
        TILE_ELI(t0, e_, li_);
        int lb = e_ * NTOK + li_ * 128;
        int v0 = min(128, cnt[e_] - li_ * 128);
        nx_token = 0; nx_gate = 0.f;
        if (row < v0) { nx_token = tokl[lb + row]; nx_gate = gatel[lb + row]; }
        const char* src = (const char*)(x + (size_t)nx_token * HDIM + q * 32);
#pragma unroll
        for (int i = 0; i < 8; i++)
            cpa16(stage_b + (uint32_t)(((i + tid) & 7) * 16), src + i * 16);
        asm volatile("cp.async.commit_group;" ::: "memory");
    }

    int cur_e = -1;
    for (int t = t0; t < t1; t++) {
        int e, li;
        TILE_ELI(t, e, li);
        const int valid = min(128, cnt[e] - li * 128);
        const unsigned token = nx_token;
        const float gv = nx_gate;

        if (t + 1 < t1) {
            int en, lin;
            TILE_ELI(t + 1, en, lin);
            int lbn = en * NTOK + lin * 128;
            int vn = min(128, cnt[en] - lin * 128);
            nx_token = 0; nx_gate = 0.f;
            if (row < vn) { nx_token = tokl[lbn + row]; nx_gate = gatel[lbn + row]; }
        }

        __syncthreads();   // prev GEMM done: A & W writable

        if (e != cur_e) {
            const float4* wgl = (const float4*)(we + (size_t)e * HDIM * ODIM);
            for (int i = tid; i < HDIM * 32; i += NTHR_F) {
                float4 v = wgl[i];
                int h = i >> 5, o4 = (i & 31);
                uint32_t h0, l0, h1, l1;
                split2(v.x, v.y, h0, l0);
                split2(v.z, v.w, h1, l1);
                uint32_t off = (uint32_t)h * WPITCH + (uint32_t)o4 * 8;
                *(uint2*)(smraw + F_WHI + off) = make_uint2(h0, h1);
                *(uint2*)(smraw + F_WLO + off) = make_uint2(l0, l1);
            }
            cur_e = e;
        }

        // convert own staged 32 floats -> A hi/lo
        asm volatile("cp.async.wait_group 0;" ::: "memory");
        if (q == 0) {
            stok[row] = (int)token;
            if (p == 0) smeta[row] = g_meta[token];
        }
        {
            uint32_t abase = (uint32_t)row * WPITCH + (uint32_t)q * 64;
#pragma unroll
            for (int i = 0; i < 8; i++) {
                float4 v = *(const float4*)(stage_l + ((i + tid) & 7) * 16);
                uint32_t h0, l0, h1, l1;
                split2(gv * v.x, gv * v.y, h0, l0);
                split2(gv * v.z, gv * v.w, h1, l1);
                *(uint2*)(smraw + F_AHI + abase + i * 8) = make_uint2(h0, h1);
                *(uint2*)(smraw + F_ALO + abase + i * 8) = make_uint2(l0, l1);
            }
        }
        // prefetch t+1 x rows (overlaps GEMM)
        if (t + 1 < t1) {
            const char* src = (const char*)(x + (size_t)nx_token * HDIM + q * 32);
#pragma unroll
            for (int i = 0; i < 8; i++)
                cpa16(stage_b + (uint32_t)(((i + tid) & 7) * 16), src + i * 16);
        }
        asm volatile("cp.async.commit_group;" ::: "memory");
        __syncthreads();   // A ready

        // GEMM: 2 m16 x 4 n8, B via x4.trans (2 n-tiles per ldsm)
        float acc[2][4][4], accB[2][4][4];
#pragma unroll
        for (int m = 0; m < 2; m++)
#pragma unroll
            for (int nt = 0; nt < 4; nt++)
#pragma unroll
                for (int j = 0; j < 4; j++) {
                    acc[m][nt][j] = 0.f; accB[m][nt][j] = 0.f;
                }

#pragma unroll
        for (int kb = 0; kb < 8; kb++) {
            uint32_t ah[2][4], al[2][4];
            uint32_t aa0 = a_base0 + (uint32_t)kb * 32;
            uint32_t aa1 = a_base1 + (uint32_t)kb * 32;
            ldsm_x4(ah[0][0], ah[0][1], ah[0][2], ah[0][3], aa0);
            ldsm_x4(al[0][0], al[0][1], al[0][2], al[0][3], aa0 + (F_ALO - F_AHI));
            ldsm_x4(ah[1][0], ah[1][1], ah[1][2], ah[1][3], aa1);
            ldsm_x4(al[1][0], al[1][1], al[1][2], al[1][3], aa1 + (F_ALO - F_AHI));
            uint32_t bb = b_base + (uint32_t)kb * 16 * WPITCH;
#pragma unroll
            for (int nt = 0; nt < 4; nt += 2) {
                uint32_t bh0, bh1, bh2, bh3, bl0, bl1, bl2, bl3;
                ldsm_x4t(bh0, bh1, bh2, bh3, bb + nt * 16);
                ldsm_x4t(bl0, bl1, bl2, bl3, bb + nt * 16 + (F_WLO - F_WHI));
#pragma unroll
                for (int m = 0; m < 2; m++) {
                    mma16816(acc[m][nt], ah[m][0], ah[m][1], ah[m][2], ah[m][3],
                             bh0, bh1);
                    mma16816(accB[m][nt], ah[m][0], ah[m][1], ah[m][2], ah[m][3],
                             bl0, bl1);
                    mma16816(accB[m][nt], al[m][0], al[m][1], al[m][2], al[m][3],
                             bh0, bh1);
                    mma16816(acc[m][nt + 1], ah[m][0], ah[m][1], ah[m][2], ah[m][3],
                             bh2, bh3);
                    mma16816(accB[m][nt + 1], ah[m][0], ah[m][1], ah[m][2], ah[m][3],
                             bl2, bl3);
                    mma16816(accB[m][nt + 1], al[m][0], al[m][1], al[m][2], al[m][3],
                             bh2, bh3);
                }
            }
        }

        // epilogue
        const int qr = lane >> 2, qk = (lane & 3) * 2;
#pragma unroll
        for (int m = 0; m < 2; m++) {
            int ra = mt * 32 + m * 16 + qr;
            int rb = ra + 8;
            bool va = ra < valid, vb = rb < valid;
            float* opa = va ? out + (size_t)stok[ra] * ODIM : 0;
            float* opb = vb ? out + (size_t)stok[rb] * ODIM : 0;
            if (p == 0) {
#pragma unroll
                for (int hrow = 0; hrow < 2; hrow++) {
                    int r = hrow ? rb : ra;
                    float* op = hrow ? opb : opa;
                    if (!(hrow ? vb : va)) continue;
                    float4 mm = smeta[r];
                    unsigned u = __float_as_uint(mm.x);
                    const float* b0p = sbias + (u & 0xff) * ODIM;
                    const float* b1p = sbias + ((u >> 8) & 0xff) * ODIM;
                    float gg0 = mm.y, gg1 = mm.z;
                    const int ci = hrow * 2;
#pragma unroll
                    for (int nt = 0; nt < 4; nt++) {
                        int col = nq * 32 + nt * 8 + qk;
                        float2 v;
                        v.x = acc[m][nt][ci] + accB[m][nt][ci]
                            + gg0 * b0p[col] + gg1 * b1p[col];
                        v.y = acc[m][nt][ci + 1] + accB[m][nt][ci + 1]
                            + gg0 * b0p[col + 1] + gg1 * b1p[col + 1];
                        *(float2*)(op + col) = v;
                    }
                }
            } else {
                float2 o[2][4];
#pragma unroll
                for (int nt = 0; nt < 4; nt++) {
                    int col = nq * 32 + nt * 8 + qk;
                    if (va) o[0][nt] = *(float2*)(opa + col);
                    if (vb) o[1][nt] = *(float2*)(opb + col);
                }
#pragma unroll
                for (int nt = 0; nt < 4; nt++) {
                    int col = nq * 32 + nt * 8 + qk;
                    if (va) {
                        float2 v = o[0][nt];
                        v.x += acc[m][nt][0] + accB[m][nt][0];
                        v.y += acc[m][nt][1] + accB[m][nt][1];
                        *(float2*)(opa + col) = v;
                    }
                    if (vb) {
                        float2 v = o[1][nt];
                        v.x += acc[m][nt][2] + accB[m][nt][2];
                        v.y += acc[m][nt][3] + accB[m][nt][3];
                        *(float2*)(opb + col) = v;
                    }
                }
            }
        }
    }
}

// ---------------- launch ----------------
extern "C" void kernel_launch(void* const* d_in, const int* in_sizes, int n_in,
                              void* d_out, int out_size) {
    const float* x  = (const float*)d_in[0];
    const float* wg = (const float*)d_in[1];
    // d_in[2] = w_noise (inactive in eval mode)
    const float* we = (const float*)d_in[3];
    const float* be = (const float*)d_in[4];
    float* out = (float*)d_out;

    cudaFuncSetAttribute(k_gate, cudaFuncAttributeMaxDynamicSharedMemorySize,
                         G_SMEM);
    cudaFuncSetAttribute(k_ffn, cudaFuncAttributeMaxDynamicSharedMemorySize,
                         F_SMEM);

    k_zero<<<1, 32>>>();
    k_gate<<<NBLK, 128, G_SMEM>>>(x, wg);
    k_ffn<<<GRID3, NTHR_F, F_SMEM>>>(x, we, be, out, 0);
    k_ffn<<<GRID3, NTHR_F, F_SMEM>>>(x, we, be, out, 1);
}